// round 3
// baseline (speedup 1.0000x reference)
#include <cuda_runtime.h>
#include <cuda_bf16.h>

// Haar wavelet 2x2 transform — persistent grid-stride version.
// Input:  x[B=8, C=64, H=512, W=512] fp32
// Output: out[B=8, 4*C=256, H/2=256, W/2=256] fp32
// out channel = 4*c + band, band in {ll, lh, hl, hh}.
//
// Per-iteration work item = 4 output columns (one float4 per plane):
// reads 2 rows x 2 float4 (MLP=4, fully coalesced), writes 4x float4.
// 1184 persistent CTAs (148 SMs x 8) stream through all 8,388,608 items.

#define B_ 8
#define C_ 64
#define H_ 512
#define W_ 512
#define H2_ (H_ / 2)
#define W2_ (W_ / 2)
#define NCOLS 4                       // output columns per item
#define WGROUPS (W2_ / NCOLS)         // 64 column-groups per output row
#define TOTAL_ITEMS ((long long)B_ * C_ * H2_ * WGROUPS)  // 8,388,608
#define NBLOCKS 1184                  // 148 SMs * 8 CTAs
#define NTHREADS 256

__global__ __launch_bounds__(NTHREADS)
void haar_kernel(const float* __restrict__ x, float* __restrict__ out) {
    const long long stride = (long long)NBLOCKS * NTHREADS;
    for (long long idx = (long long)blockIdx.x * NTHREADS + threadIdx.x;
         idx < TOTAL_ITEMS; idx += stride) {

        int wg = (int)(idx & (WGROUPS - 1));   // / % 64
        long long t = idx >> 6;
        int h2 = (int)(t & (H2_ - 1));         // % 256
        t >>= 8;
        int c = (int)(t & (C_ - 1));           // % 64
        int b = (int)(t >> 6);

        const long long in_plane = (long long)(b * C_ + c) * (H_ * W_);
        const long long in_row0 = in_plane + (long long)(2 * h2) * W_ + (long long)(2 * NCOLS) * wg;
        const long long in_row1 = in_row0 + W_;

        float4 r0a = *reinterpret_cast<const float4*>(x + in_row0);
        float4 r0b = *reinterpret_cast<const float4*>(x + in_row0 + 4);
        float4 r1a = *reinterpret_cast<const float4*>(x + in_row1);
        float4 r1b = *reinterpret_cast<const float4*>(x + in_row1 + 4);

        float x00[4] = {r0a.x, r0a.z, r0b.x, r0b.z};
        float x01[4] = {r0a.y, r0a.w, r0b.y, r0b.w};
        float x10[4] = {r1a.x, r1a.z, r1b.x, r1b.z};
        float x11[4] = {r1a.y, r1a.w, r1b.y, r1b.w};

        float4 ll, lh, hl, hh;
        float* llp = &ll.x; float* lhp = &lh.x; float* hlp = &hl.x; float* hhp = &hh.x;
        #pragma unroll
        for (int j = 0; j < 4; ++j) {
            float s0 = x00[j] + x01[j];
            float s1 = x10[j] + x11[j];
            float d0 = x01[j] - x00[j];
            float d1 = x11[j] - x10[j];
            llp[j] = 0.5f * (s0 + s1);
            lhp[j] = 0.5f * (s1 - s0);
            hlp[j] = 0.5f * (d0 + d1);
            hhp[j] = 0.5f * (d1 - d0);
        }

        const long long out_base =
            ((long long)(b * (4 * C_) + 4 * c) * H2_ + h2) * W2_ + (long long)NCOLS * wg;
        const long long ps = (long long)H2_ * W2_;

        *reinterpret_cast<float4*>(out + out_base)          = ll;
        *reinterpret_cast<float4*>(out + out_base + ps)     = lh;
        *reinterpret_cast<float4*>(out + out_base + 2 * ps) = hl;
        *reinterpret_cast<float4*>(out + out_base + 3 * ps) = hh;
    }
}

extern "C" void kernel_launch(void* const* d_in, const int* in_sizes, int n_in,
                              void* d_out, int out_size) {
    const float* x = (const float*)d_in[0];
    float* out = (float*)d_out;
    haar_kernel<<<NBLOCKS, NTHREADS>>>(x, out);
}

// round 4
// speedup vs baseline: 1.1233x; 1.1233x over previous
#include <cuda_runtime.h>
#include <cuda_bf16.h>

// Haar wavelet 2x2 transform — R1 flat skeleton + streaming cache hints.
// Input:  x[B=8, C=64, H=512, W=512] fp32
// Output: out[B=8, 4*C=256, H/2=256, W/2=256] fp32
// out channel = 4*c + band, band in {ll, lh, hl, hh}.
// One thread = 4 output columns: 4x float4 loads (MLP=4), 4x float4 stores.

#define B_ 8
#define C_ 64
#define H_ 512
#define W_ 512
#define H2_ (H_ / 2)
#define W2_ (W_ / 2)
#define NCOLS 4                          // output columns per thread
#define WGROUPS (W2_ / NCOLS)            // 64 column-groups per output row

__global__ __launch_bounds__(256)
void haar_kernel(const float* __restrict__ x, float* __restrict__ out) {
    long long idx = (long long)blockIdx.x * blockDim.x + threadIdx.x;
    // total = B*C*H2*WGROUPS = 8*64*256*64 = 8,388,608
    int wg = (int)(idx & (WGROUPS - 1));
    long long t = idx >> 6;
    int h2 = (int)(t & (H2_ - 1));
    t >>= 8;
    int c = (int)(t & (C_ - 1));
    int b = (int)(t >> 6);

    const long long in_plane = (long long)(b * C_ + c) * (H_ * W_);
    const long long in_row0 = in_plane + (long long)(2 * h2) * W_ + (long long)(2 * NCOLS) * wg;
    const long long in_row1 = in_row0 + W_;

    // 8 consecutive floats per row = 2x float4, evict-first streaming loads.
    float4 r0a = __ldcs(reinterpret_cast<const float4*>(x + in_row0));
    float4 r0b = __ldcs(reinterpret_cast<const float4*>(x + in_row0) + 1);
    float4 r1a = __ldcs(reinterpret_cast<const float4*>(x + in_row1));
    float4 r1b = __ldcs(reinterpret_cast<const float4*>(x + in_row1) + 1);

    float x00[4] = {r0a.x, r0a.z, r0b.x, r0b.z};
    float x01[4] = {r0a.y, r0a.w, r0b.y, r0b.w};
    float x10[4] = {r1a.x, r1a.z, r1b.x, r1b.z};
    float x11[4] = {r1a.y, r1a.w, r1b.y, r1b.w};

    float4 ll, lh, hl, hh;
    float* llp = &ll.x; float* lhp = &lh.x; float* hlp = &hl.x; float* hhp = &hh.x;
    #pragma unroll
    for (int j = 0; j < 4; ++j) {
        float s0 = x00[j] + x01[j];
        float s1 = x10[j] + x11[j];
        float d0 = x01[j] - x00[j];
        float d1 = x11[j] - x10[j];
        llp[j] = 0.5f * (s0 + s1);
        lhp[j] = 0.5f * (s1 - s0);
        hlp[j] = 0.5f * (d0 + d1);
        hhp[j] = 0.5f * (d1 - d0);
    }

    const long long out_base =
        ((long long)(b * (4 * C_) + 4 * c) * H2_ + h2) * W2_ + (long long)NCOLS * wg;
    const long long ps = (long long)H2_ * W2_;   // plane stride

    __stcs(reinterpret_cast<float4*>(out + out_base),          ll);
    __stcs(reinterpret_cast<float4*>(out + out_base + ps),     lh);
    __stcs(reinterpret_cast<float4*>(out + out_base + 2 * ps), hl);
    __stcs(reinterpret_cast<float4*>(out + out_base + 3 * ps), hh);
}

extern "C" void kernel_launch(void* const* d_in, const int* in_sizes, int n_in,
                              void* d_out, int out_size) {
    const float* x = (const float*)d_in[0];
    float* out = (float*)d_out;
    const long long total_threads = (long long)B_ * C_ * H2_ * WGROUPS; // 8,388,608
    const int threads = 256;
    const int blocks = (int)((total_threads + threads - 1) / threads); // 32768
    haar_kernel<<<blocks, threads>>>(x, out);
}

// round 5
// speedup vs baseline: 1.1339x; 1.0094x over previous
#include <cuda_runtime.h>
#include <cuda_bf16.h>

// Haar wavelet 2x2 transform — fully warp-dense load/store pattern.
// Input:  x[B=8, C=64, H=512, W=512] fp32
// Output: out[B=8, 4*C=256, H/2=256, W/2=256] fp32
// out channel = 4*c + band, band in {ll, lh, hl, hh}.
//
// One thread = 2 output columns (1 float2 per plane):
//   loads  : float4 at input col 4g of row 2*h2 and row 2*h2+1
//            -> lane-dense: one LDG.128 covers 512 B contiguous per warp
//   stores : float2 at output col 2g on each of 4 planes
//            -> lane-dense: one STG.64 covers 256 B contiguous per warp
// Every memory instruction touches each 128B line exactly once (1 wavefront/line).

#define B_ 8
#define C_ 64
#define H_ 512
#define W_ 512
#define H2_ (H_ / 2)
#define W2_ (W_ / 2)
#define GROUPS (W2_ / 2)              // 128 two-column groups per output row

__global__ __launch_bounds__(256)
void haar_kernel(const float* __restrict__ x, float* __restrict__ out) {
    long long idx = (long long)blockIdx.x * blockDim.x + threadIdx.x;
    // total = B*C*H2*GROUPS = 8*64*256*128 = 16,777,216
    int g  = (int)(idx & (GROUPS - 1));     // % 128
    long long t = idx >> 7;
    int h2 = (int)(t & (H2_ - 1));          // % 256
    t >>= 8;
    int c  = (int)(t & (C_ - 1));           // % 64
    int b  = (int)(t >> 6);

    const long long in_plane = (long long)(b * C_ + c) * (H_ * W_);
    const long long in_row0  = in_plane + (long long)(2 * h2) * W_ + 4LL * g;
    const long long in_row1  = in_row0 + W_;

    float4 r0 = *reinterpret_cast<const float4*>(x + in_row0);
    float4 r1 = *reinterpret_cast<const float4*>(x + in_row1);

    // Column j=0: pair (r.x, r.y); column j=1: pair (r.z, r.w)
    float s0x = r0.x + r0.y,  s0z = r0.z + r0.w;   // row0 sums
    float s1x = r1.x + r1.y,  s1z = r1.z + r1.w;   // row1 sums
    float d0x = r0.y - r0.x,  d0z = r0.w - r0.z;   // row0 diffs
    float d1x = r1.y - r1.x,  d1z = r1.w - r1.z;   // row1 diffs

    float2 ll = make_float2(0.5f * (s0x + s1x), 0.5f * (s0z + s1z));
    float2 lh = make_float2(0.5f * (s1x - s0x), 0.5f * (s1z - s0z));
    float2 hl = make_float2(0.5f * (d0x + d1x), 0.5f * (d0z + d1z));
    float2 hh = make_float2(0.5f * (d1x - d0x), 0.5f * (d1z - d0z));

    const long long out_base =
        ((long long)(b * (4 * C_) + 4 * c) * H2_ + h2) * W2_ + 2LL * g;
    const long long ps = (long long)H2_ * W2_;   // plane stride

    *reinterpret_cast<float2*>(out + out_base)          = ll;
    *reinterpret_cast<float2*>(out + out_base + ps)     = lh;
    *reinterpret_cast<float2*>(out + out_base + 2 * ps) = hl;
    *reinterpret_cast<float2*>(out + out_base + 3 * ps) = hh;
}

extern "C" void kernel_launch(void* const* d_in, const int* in_sizes, int n_in,
                              void* d_out, int out_size) {
    const float* x = (const float*)d_in[0];
    float* out = (float*)d_out;
    const long long total_threads = (long long)B_ * C_ * H2_ * GROUPS; // 16,777,216
    const int threads = 256;
    const int blocks = (int)(total_threads / threads);                  // 65536
    haar_kernel<<<blocks, threads>>>(x, out);
}